// round 12
// baseline (speedup 1.0000x reference)
#include <cuda_runtime.h>

#define BB   32
#define TT   4096
#define DD   512
#define GG   8
#define OO   512
#define CHUNK 128
#define NCHUNK (TT/CHUNK)   // 32

// Scratch (__device__ globals; no allocations allowed)
__device__ float d_sums[BB*GG*DD];
__device__ int   d_counts[BB*GG];
__device__ int   d_st[TT];      // token ids, group-sorted (shared across b)
__device__ int   d_sg[TT];      // group id per sorted slot

// ---------------------------------------------------------------- sort+zero
// grid=33: CTA 0 sorts the (batch-independent) token list by group with
// warp-per-group ballot compaction; CTAs 1..32 zero one b's sums slice and
// counts in parallel. One launch instead of two.
__global__ void __launch_bounds__(256) k_sort(const int* __restrict__ tt) {
    int tid = threadIdx.x;

    if (blockIdx.x != 0) {
        int b = blockIdx.x - 1;
        float4* sz = (float4*)&d_sums[(size_t)b*GG*DD];
        #pragma unroll
        for (int k = 0; k < 4; k++)
            sz[tid + k*256] = make_float4(0.f,0.f,0.f,0.f);
        if (tid < GG) d_counts[b*GG + tid] = 0;
        return;
    }

    __shared__ int s_cnt[GG];
    int lane = tid & 31;
    int w    = tid >> 5;          // warp == group

    int c = 0;
    #pragma unroll 4
    for (int t0 = 0; t0 < TT; t0 += 32)
        c += (tt[t0 + lane] == w);
    #pragma unroll
    for (int off = 16; off > 0; off >>= 1)
        c += __shfl_down_sync(0xffffffffu, c, off);
    if (lane == 0) s_cnt[w] = c;
    __syncthreads();

    int base = 0;
    #pragma unroll
    for (int g = 0; g < GG; g++) base += (g < w) ? s_cnt[g] : 0;

    int pos = base;
    for (int t0 = 0; t0 < TT; t0 += 32) {
        int g = tt[t0 + lane];
        unsigned m = __ballot_sync(0xffffffffu, g == w);
        if (g == w) {
            int r = __popc(m & ((1u << lane) - 1u));
            d_st[pos + r] = t0 + lane;
            d_sg[pos + r] = w;
        }
        pos += __popc(m);
    }
}

// ------------------------------------------------------------- masked sums
// grid (NCHUNK, BB), 256 threads (R4-measured-best variant). Warp-uniform
// predicated loads, 8-wide front-batched; atomic flush at group boundaries.
__device__ __forceinline__ void flush_acc(int b, int g, int lane, float4 a) {
    float* dst = &d_sums[((size_t)b*GG + g)*DD + lane*4];
    atomicAdd(dst+0, a.x); atomicAdd(dst+1, a.y);
    atomicAdd(dst+2, a.z); atomicAdd(dst+3, a.w);
}

__global__ void __launch_bounds__(256) k_main(const float* __restrict__ batch,
                                              const int* __restrict__ pad) {
    __shared__ int s_tok[CHUNK];
    __shared__ int s_grp[CHUNK];
    __shared__ int s_val[CHUNK];

    int b   = blockIdx.y;
    int c0  = blockIdx.x * CHUNK;
    int tid = threadIdx.x;

    if (tid < CHUNK) {
        int t = d_st[c0 + tid];
        s_tok[tid] = t;
        s_grp[tid] = d_sg[c0 + tid];
        s_val[tid] = pad[(size_t)b*TT + t] ? 0 : 1;   // bool -> int32 transport
    }
    __syncthreads();

    // per-(b,g) valid counts: 64 threads, 16 smem reads each
    if (tid < 64) {
        int g = tid >> 3, j = tid & 7;
        int c = 0;
        #pragma unroll
        for (int k = 0; k < 16; k++) {
            int i = j*16 + k;
            c += (s_grp[i] == g) & s_val[i];
        }
        if (c) atomicAdd(&d_counts[b*GG + g], c);
    }

    int lane = tid & 127;
    int half = tid >> 7;
    const float4* bb = (const float4*)(batch + (size_t)b * TT * DD);

    float4 acc = make_float4(0.f,0.f,0.f,0.f);
    int curg = s_grp[0];

    #define PLOAD(V, J)                                                     \
        float4 V = make_float4(0.f,0.f,0.f,0.f);                            \
        if (s_val[i + 2*(J)])                                               \
            V = __ldcs(&bb[(size_t)s_tok[i + 2*(J)] * (DD/4) + lane]);

    #define ACCSTEP(J, V)                                                   \
        { int g_ = s_grp[i + 2*(J)];                                        \
          if (g_ != curg) {                                                 \
              flush_acc(b, curg, lane, acc);                                \
              acc = make_float4(0.f,0.f,0.f,0.f); curg = g_; }              \
          acc.x += (V).x; acc.y += (V).y; acc.z += (V).z; acc.w += (V).w; }

    #pragma unroll
    for (int s = 0; s < 8; s++) {
        int i = half + s*16;
        PLOAD(v0, 0) PLOAD(v1, 1) PLOAD(v2, 2) PLOAD(v3, 3)
        PLOAD(v4, 4) PLOAD(v5, 5) PLOAD(v6, 6) PLOAD(v7, 7)
        ACCSTEP(0, v0); ACCSTEP(1, v1); ACCSTEP(2, v2); ACCSTEP(3, v3);
        ACCSTEP(4, v4); ACCSTEP(5, v5); ACCSTEP(6, v6); ACCSTEP(7, v7);
    }
    flush_acc(b, curg, lane, acc);
    #undef PLOAD
    #undef ACCSTEP
}

// ------------------------------------------------------ means -> GEMM + bias
// R10-exact (measured best: 16.2us). grid (8 g, 16 o-blocks of 32) = 128
// CTAs, 512 threads. warp = one d-slice of 32 (d warp-uniform), lanes = 32
// consecutive o. Phase 1: transpose-divide means into smem [d][b] (pad 36).
// Phase 2: front-batch 32 W loads into registers, 1024 FFMAs vs broadcast
// LDS.128 mean reads. Phase 3: slice reduction via padded smem + bias.
#define GOB  32              // o per CTA
#define NSL  16              // d-slices (= warps)
#define SLD  (DD/NSL)        // 32 d per slice
#define MTP  36              // padded b-row (16B-aligned, conflict-spread)
#define GEMM_SMEM ((DD*MTP + NSL*GOB*MTP) * 4)   // 147456 B

__global__ void __launch_bounds__(512) k_gemm(const float* __restrict__ W,
                                              const float* __restrict__ bias,
                                              float* __restrict__ out) {
    extern __shared__ float sm[];
    float* s_mt  = sm;               // [512][36]  means^T: [d][b]
    float* s_red = sm + DD*MTP;      // [16][32][36] slice partials

    __shared__ float s_inv[BB];

    int g   = blockIdx.x;
    int o0  = blockIdx.y * GOB;
    int tid = threadIdx.x;

    if (tid < BB) {
        int c = d_counts[tid*GG + g];
        s_inv[tid] = (c > 0) ? 1.0f / (float)c : 0.0f;
    }
    __syncthreads();

    // transpose-divide: 32b x 512d, coalesced loads
    for (int idx = tid; idx < BB*DD; idx += 512) {
        int b = idx >> 9;
        int d = idx & (DD-1);
        float s = d_sums[((size_t)b*GG + g)*DD + d];
        s_mt[d*MTP + b] = s * s_inv[b];
    }
    __syncthreads();

    int o  = tid & 31;          // lane -> output column
    int sl = tid >> 5;          // warp -> d-slice
    int d0 = sl * SLD;

    // front-batched W strip: 32 coalesced LDG.32, one DRAM round-trip
    const float* wp = W + ((size_t)g*DD + d0)*OO + o0 + o;
    float wreg[SLD];
    #pragma unroll
    for (int k = 0; k < SLD; k++)
        wreg[k] = __ldg(wp + (size_t)k*OO);

    float acc[BB];
    #pragma unroll
    for (int b = 0; b < BB; b++) acc[b] = 0.f;

    #pragma unroll
    for (int k = 0; k < SLD; k++) {
        const float4* mrow = (const float4*)(s_mt + (d0 + k)*MTP);
        float w = wreg[k];
        #pragma unroll
        for (int j = 0; j < 8; j++) {
            float4 m = mrow[j];                    // broadcast LDS.128
            acc[j*4+0] = fmaf(m.x, w, acc[j*4+0]);
            acc[j*4+1] = fmaf(m.y, w, acc[j*4+1]);
            acc[j*4+2] = fmaf(m.z, w, acc[j*4+2]);
            acc[j*4+3] = fmaf(m.w, w, acc[j*4+3]);
        }
    }

    // stash slice partials: [sl][o][b], padded row
    float* rp = s_red + (sl*GOB + o)*MTP;
    #pragma unroll
    for (int j = 0; j < 8; j++)
        ((float4*)rp)[j] = make_float4(acc[j*4], acc[j*4+1],
                                       acc[j*4+2], acc[j*4+3]);
    __syncthreads();

    // reduce 16 slices; consecutive threads = consecutive o -> coalesced STG
    for (int idx = tid; idx < GOB*BB; idx += 512) {
        int oo = idx & 31;
        int b  = idx >> 5;
        float s = 0.f;
        #pragma unroll
        for (int sl2 = 0; sl2 < NSL; sl2++)
            s += s_red[(sl2*GOB + oo)*MTP + b];
        out[((size_t)b*GG + g)*OO + o0 + oo] =
            s + bias[(size_t)g*OO + o0 + oo];
    }
}

// ---------------------------------------------------------------- launcher
// metadata order: batch(f32), W(f32), b_bias(f32), token_types(i32),
//                 key_padding_mask(bool -> int32)
extern "C" void kernel_launch(void* const* d_in, const int* in_sizes, int n_in,
                              void* d_out, int out_size) {
    const float* batch = (const float*)d_in[0];
    const float* W     = (const float*)d_in[1];
    const float* bias  = (const float*)d_in[2];
    const int*   tt    = (const int*)d_in[3];
    const int*   pad   = (const int*)d_in[4];
    float* out = (float*)d_out;

    cudaFuncSetAttribute(k_gemm, cudaFuncAttributeMaxDynamicSharedMemorySize,
                         GEMM_SMEM);

    k_sort<<<BB + 1, 256>>>(tt);

    dim3 gmain(NCHUNK, BB);
    k_main<<<gmain, 256>>>(batch, pad);

    dim3 ggemm(GG, OO/GOB);
    k_gemm<<<ggemm, 512, GEMM_SMEM>>>(W, bias, out);
}

// round 13
// speedup vs baseline: 1.5955x; 1.5955x over previous
#include <cuda_runtime.h>

#define BB   32
#define TT   4096
#define DD   512
#define GG   8
#define OO   512
#define CHUNK 128
#define NCHUNK (TT/CHUNK)   // 32

// Scratch (__device__ globals; no allocations allowed)
__device__ float d_sums[BB*GG*DD];
__device__ int   d_counts[BB*GG];
__device__ int   d_st[TT];      // token ids, group-sorted (shared across b)
__device__ int   d_sg[TT];      // group id per sorted slot

// ---------------------------------------------------------------- prep
// grid=40: CTAs 0..31 zero one b's sums slice + counts. CTAs 32..39 are
// sort-CTAs, one per group g: full-parallel compaction of group g's token
// ids (16 coalesced loads into regs, 8-group histogram, 16 register-resident
// ballot steps). No serial global walk, no single lonely CTA.
__global__ void __launch_bounds__(256) k_prep(const int* __restrict__ tt) {
    int tid = threadIdx.x;
    int bid = blockIdx.x;

    if (bid < BB) {
        float4* sz = (float4*)&d_sums[(size_t)bid*GG*DD];
        #pragma unroll
        for (int k = 0; k < 4; k++)
            sz[tid + k*256] = make_float4(0.f,0.f,0.f,0.f);
        if (tid < GG) d_counts[bid*GG + tid] = 0;
        return;
    }

    int g    = bid - BB;            // my group
    int lane = tid & 31;
    int w    = tid >> 5;
    __shared__ int s_hist[8][GG];   // [warp][group]

    // load 16 tokens (coalesced), count all 8 groups in registers
    int myg[16];
    int c[GG];
    #pragma unroll
    for (int q = 0; q < GG; q++) c[q] = 0;
    #pragma unroll
    for (int k = 0; k < 16; k++) {
        int t = tt[tid + k*256];
        myg[k] = t;
        #pragma unroll
        for (int q = 0; q < GG; q++) c[q] += (t == q);
    }
    // warp-reduce each of the 8 counters
    #pragma unroll
    for (int q = 0; q < GG; q++) {
        #pragma unroll
        for (int off = 16; off > 0; off >>= 1)
            c[q] += __shfl_down_sync(0xffffffffu, c[q], off);
        if (lane == 0) s_hist[w][q] = c[q];
    }
    __syncthreads();

    // base = start of group g region + my warp's offset within it
    int base = 0;
    #pragma unroll
    for (int ww = 0; ww < 8; ww++) {
        #pragma unroll
        for (int q = 0; q < GG; q++) {
            int v = s_hist[ww][q];
            base += (q < g) ? v : 0;
            base += (q == g && ww < w) ? v : 0;
        }
    }

    // scatter: 16 ballot-compaction steps, all operands in registers
    int wpos = base;
    #pragma unroll
    for (int k = 0; k < 16; k++) {
        bool hit = (myg[k] == g);
        unsigned m = __ballot_sync(0xffffffffu, hit);
        if (hit) {
            int r = __popc(m & ((1u << lane) - 1u));
            d_st[wpos + r] = tid + k*256;
            d_sg[wpos + r] = g;
        }
        wpos += __popc(m);
    }
}

// ------------------------------------------------------------- masked sums
// grid (NCHUNK, BB), 256 threads (R4-measured-best variant). Warp-uniform
// predicated loads, 8-wide front-batched; atomic flush at group boundaries.
__device__ __forceinline__ void flush_acc(int b, int g, int lane, float4 a) {
    float* dst = &d_sums[((size_t)b*GG + g)*DD + lane*4];
    atomicAdd(dst+0, a.x); atomicAdd(dst+1, a.y);
    atomicAdd(dst+2, a.z); atomicAdd(dst+3, a.w);
}

__global__ void __launch_bounds__(256) k_main(const float* __restrict__ batch,
                                              const int* __restrict__ pad) {
    __shared__ int s_tok[CHUNK];
    __shared__ int s_grp[CHUNK];
    __shared__ int s_val[CHUNK];

    int b   = blockIdx.y;
    int c0  = blockIdx.x * CHUNK;
    int tid = threadIdx.x;

    if (tid < CHUNK) {
        int t = d_st[c0 + tid];
        s_tok[tid] = t;
        s_grp[tid] = d_sg[c0 + tid];
        s_val[tid] = pad[(size_t)b*TT + t] ? 0 : 1;   // bool -> int32 transport
    }
    __syncthreads();

    // per-(b,g) valid counts: 64 threads, 16 smem reads each
    if (tid < 64) {
        int g = tid >> 3, j = tid & 7;
        int c = 0;
        #pragma unroll
        for (int k = 0; k < 16; k++) {
            int i = j*16 + k;
            c += (s_grp[i] == g) & s_val[i];
        }
        if (c) atomicAdd(&d_counts[b*GG + g], c);
    }

    int lane = tid & 127;
    int half = tid >> 7;
    const float4* bb = (const float4*)(batch + (size_t)b * TT * DD);

    float4 acc = make_float4(0.f,0.f,0.f,0.f);
    int curg = s_grp[0];

    #define PLOAD(V, J)                                                     \
        float4 V = make_float4(0.f,0.f,0.f,0.f);                            \
        if (s_val[i + 2*(J)])                                               \
            V = __ldcs(&bb[(size_t)s_tok[i + 2*(J)] * (DD/4) + lane]);

    #define ACCSTEP(J, V)                                                   \
        { int g_ = s_grp[i + 2*(J)];                                        \
          if (g_ != curg) {                                                 \
              flush_acc(b, curg, lane, acc);                                \
              acc = make_float4(0.f,0.f,0.f,0.f); curg = g_; }              \
          acc.x += (V).x; acc.y += (V).y; acc.z += (V).z; acc.w += (V).w; }

    #pragma unroll
    for (int s = 0; s < 8; s++) {
        int i = half + s*16;
        PLOAD(v0, 0) PLOAD(v1, 1) PLOAD(v2, 2) PLOAD(v3, 3)
        PLOAD(v4, 4) PLOAD(v5, 5) PLOAD(v6, 6) PLOAD(v7, 7)
        ACCSTEP(0, v0); ACCSTEP(1, v1); ACCSTEP(2, v2); ACCSTEP(3, v3);
        ACCSTEP(4, v4); ACCSTEP(5, v5); ACCSTEP(6, v6); ACCSTEP(7, v7);
    }
    flush_acc(b, curg, lane, acc);
    #undef PLOAD
    #undef ACCSTEP
}

// ------------------------------------------------------ means -> GEMM + bias
// R10-exact (measured best: 16.2us). grid (8 g, 16 o-blocks of 32) = 128
// CTAs, 512 threads. warp = one d-slice of 32 (d warp-uniform), lanes = 32
// consecutive o. Phase 1: transpose-divide means into smem [d][b] (pad 36).
// Phase 2: front-batch 32 W loads into registers, 1024 FFMAs vs broadcast
// LDS.128 mean reads. Phase 3: slice reduction via padded smem + bias.
#define GOB  32              // o per CTA
#define NSL  16              // d-slices (= warps)
#define SLD  (DD/NSL)        // 32 d per slice
#define MTP  36              // padded b-row (16B-aligned, conflict-spread)
#define GEMM_SMEM ((DD*MTP + NSL*GOB*MTP) * 4)   // 147456 B

__global__ void __launch_bounds__(512) k_gemm(const float* __restrict__ W,
                                              const float* __restrict__ bias,
                                              float* __restrict__ out) {
    extern __shared__ float sm[];
    float* s_mt  = sm;               // [512][36]  means^T: [d][b]
    float* s_red = sm + DD*MTP;      // [16][32][36] slice partials

    __shared__ float s_inv[BB];

    int g   = blockIdx.x;
    int o0  = blockIdx.y * GOB;
    int tid = threadIdx.x;

    if (tid < BB) {
        int c = d_counts[tid*GG + g];
        s_inv[tid] = (c > 0) ? 1.0f / (float)c : 0.0f;
    }
    __syncthreads();

    // transpose-divide: 32b x 512d, coalesced loads
    for (int idx = tid; idx < BB*DD; idx += 512) {
        int b = idx >> 9;
        int d = idx & (DD-1);
        float s = d_sums[((size_t)b*GG + g)*DD + d];
        s_mt[d*MTP + b] = s * s_inv[b];
    }
    __syncthreads();

    int o  = tid & 31;          // lane -> output column
    int sl = tid >> 5;          // warp -> d-slice
    int d0 = sl * SLD;

    // front-batched W strip: 32 coalesced LDG.32, one DRAM round-trip
    const float* wp = W + ((size_t)g*DD + d0)*OO + o0 + o;
    float wreg[SLD];
    #pragma unroll
    for (int k = 0; k < SLD; k++)
        wreg[k] = __ldg(wp + (size_t)k*OO);

    float acc[BB];
    #pragma unroll
    for (int b = 0; b < BB; b++) acc[b] = 0.f;

    #pragma unroll
    for (int k = 0; k < SLD; k++) {
        const float4* mrow = (const float4*)(s_mt + (d0 + k)*MTP);
        float w = wreg[k];
        #pragma unroll
        for (int j = 0; j < 8; j++) {
            float4 m = mrow[j];                    // broadcast LDS.128
            acc[j*4+0] = fmaf(m.x, w, acc[j*4+0]);
            acc[j*4+1] = fmaf(m.y, w, acc[j*4+1]);
            acc[j*4+2] = fmaf(m.z, w, acc[j*4+2]);
            acc[j*4+3] = fmaf(m.w, w, acc[j*4+3]);
        }
    }

    // stash slice partials: [sl][o][b], padded row
    float* rp = s_red + (sl*GOB + o)*MTP;
    #pragma unroll
    for (int j = 0; j < 8; j++)
        ((float4*)rp)[j] = make_float4(acc[j*4], acc[j*4+1],
                                       acc[j*4+2], acc[j*4+3]);
    __syncthreads();

    // reduce 16 slices; consecutive threads = consecutive o -> coalesced STG
    for (int idx = tid; idx < GOB*BB; idx += 512) {
        int oo = idx & 31;
        int b  = idx >> 5;
        float s = 0.f;
        #pragma unroll
        for (int sl2 = 0; sl2 < NSL; sl2++)
            s += s_red[(sl2*GOB + oo)*MTP + b];
        out[((size_t)b*GG + g)*OO + o0 + oo] =
            s + bias[(size_t)g*OO + o0 + oo];
    }
}

// ---------------------------------------------------------------- launcher
// metadata order: batch(f32), W(f32), b_bias(f32), token_types(i32),
//                 key_padding_mask(bool -> int32)
extern "C" void kernel_launch(void* const* d_in, const int* in_sizes, int n_in,
                              void* d_out, int out_size) {
    const float* batch = (const float*)d_in[0];
    const float* W     = (const float*)d_in[1];
    const float* bias  = (const float*)d_in[2];
    const int*   tt    = (const int*)d_in[3];
    const int*   pad   = (const int*)d_in[4];
    float* out = (float*)d_out;

    cudaFuncSetAttribute(k_gemm, cudaFuncAttributeMaxDynamicSharedMemorySize,
                         GEMM_SMEM);

    k_prep<<<BB + GG, 256>>>(tt);

    dim3 gmain(NCHUNK, BB);
    k_main<<<gmain, 256>>>(batch, pad);

    dim3 ggemm(GG, OO/GOB);
    k_gemm<<<ggemm, 512, GEMM_SMEM>>>(W, bias, out);
}